// round 7
// baseline (speedup 1.0000x reference)
#include <cuda_runtime.h>
#include <math.h>

// x[16,64,256,256] f32, w[1,2,3,3] f32
#define B_   16
#define C_   64
#define H_   256
#define W_   256
#define TH   16
#define TW   32
#define HH_  (TH + 2)          // 18
#define HW_  (TW + 2)          // 34
#define NHALO (HH_ * HW_)      // 612
#define NINT  (TH * TW)        // 512
#define NT    640
#define HWIMG (H_ * W_)
#define CHW   (C_ * HWIMG)
#define NG    (NINT / 4)       // 128 float4 groups per channel

__global__ void __launch_bounds__(NT, 3)
spatial_attention_kernel(const float* __restrict__ x,
                         const float* __restrict__ w,
                         float* __restrict__ out) {
    __shared__ float s_max[NHALO];
    __shared__ float s_avg[NHALO];
    __shared__ float s_attn[NINT];
    __shared__ float s_w[18];

    const int tid = threadIdx.x;
    const int b   = blockIdx.z;
    const int y0  = blockIdx.y * TH;
    const int x0  = blockIdx.x * TW;
    const float* __restrict__ xb = x + (size_t)b * CHW;

    if (tid < 18) s_w[tid] = w[tid];

    // ---- Phase 1: one halo pixel per thread, 64 channels, 4 acc chains --
    if (tid < NHALO) {
        const int iy = tid / HW_;
        const int ix = tid - iy * HW_;
        const int Y  = y0 - 1 + iy;
        const int X  = x0 - 1 + ix;
        const bool inb = (Y >= 0) & (Y < H_) & (X >= 0) & (X < W_);

        float s0 = 0.f, s1 = 0.f, s2 = 0.f, s3 = 0.f;
        float m0 = -1e30f, m1 = -1e30f, m2 = -1e30f, m3 = -1e30f;
        if (inb) {
            const float* __restrict__ p = xb + (size_t)Y * W_ + X;
#pragma unroll 4
            for (int c = 0; c < C_; c += 4) {
                const float v0 = __ldg(p + (size_t)c       * HWIMG);
                const float v1 = __ldg(p + (size_t)(c + 1) * HWIMG);
                const float v2 = __ldg(p + (size_t)(c + 2) * HWIMG);
                const float v3 = __ldg(p + (size_t)(c + 3) * HWIMG);
                s0 += v0; m0 = fmaxf(m0, v0);
                s1 += v1; m1 = fmaxf(m1, v1);
                s2 += v2; m2 = fmaxf(m2, v2);
                s3 += v3; m3 = fmaxf(m3, v3);
            }
        }
        s_avg[tid] = inb ? ((s0 + s1) + (s2 + s3)) * (1.0f / C_) : 0.0f;
        s_max[tid] = inb ? fmaxf(fmaxf(m0, m1), fmaxf(m2, m3)) : 0.0f;
    }
    __syncthreads();

    // ---- Phase 2: 3x3 conv (concat [max, avg]) + sigmoid ----------------
    if (tid < NINT) {
        const int y  = tid >> 5;
        const int xq = tid & 31;
        float acc = 0.0f;
#pragma unroll
        for (int dy = 0; dy < 3; dy++) {
#pragma unroll
            for (int dx = 0; dx < 3; dx++) {
                const int hi = (y + dy) * HW_ + (xq + dx);
                acc += s_w[dy * 3 + dx]     * s_max[hi];   // w ch0 -> max
                acc += s_w[9 + dy * 3 + dx] * s_avg[hi];   // w ch1 -> avg
            }
        }
        s_attn[tid] = 1.0f / (1.0f + expf(-acc));
    }
    __syncthreads();

    // ---- Phase 3: re-read tile (L2-hot), multiply, streamed stores ------
    // 512 px * 64 ch / 4 = 8192 float4; thread owns group g (0..127) and
    // channels c0, c0+5, ... (c0 in 0..4).
    const int g  = tid & 127;            // float4 group in tile
    const int c0 = tid >> 7;             // 0..4
    const int py = g >> 3;               // row 0..15
    const int px = (g & 7) * 4;          // col 0,4,..,28
    const float4 a = *reinterpret_cast<const float4*>(&s_attn[py * TW + px]);
    const size_t base = (size_t)(y0 + py) * W_ + (x0 + px);
    float* __restrict__ ob = out + (size_t)b * CHW;

    for (int c = c0; c < C_; c += 5) {
        float4 v = __ldcs(reinterpret_cast<const float4*>(xb + (size_t)c * HWIMG + base));
        v.x *= a.x; v.y *= a.y; v.z *= a.z; v.w *= a.w;
        __stcs(reinterpret_cast<float4*>(ob + (size_t)c * HWIMG + base), v);
    }
}

extern "C" void kernel_launch(void* const* d_in, const int* in_sizes, int n_in,
                              void* d_out, int out_size) {
    const float* x = (const float*)d_in[0];
    const float* w = (const float*)d_in[1];
    float* out     = (float*)d_out;

    dim3 grid(W_ / TW, H_ / TH, B_);   // (8, 16, 16) = 2048 blocks
    spatial_attention_kernel<<<grid, NT>>>(x, w, out);
}

// round 9
// speedup vs baseline: 1.1052x; 1.1052x over previous
#include <cuda_runtime.h>
#include <math.h>

// x[16,64,256,256] f32, w[1,2,3,3] f32
#define B_   16
#define C_   64
#define H_   256
#define W_   256
#define TH   8
#define TW   32
#define HH_  (TH + 2)          // 10
#define HW_  (TW + 2)          // 34
#define NHALO (HH_ * HW_)      // 340
#define NINT  (TH * TW)        // 256
#define NRING (NHALO - NINT)   // 84 ring pixels
#define NT    320
#define CH2   (C_ / 2)         // 32 channels per half
#define HWIMG (H_ * W_)
#define CHW   (C_ * HWIMG)

__global__ void __launch_bounds__(NT, 6)
spatial_attention_kernel(const float* __restrict__ x,
                         const float* __restrict__ w,
                         float* __restrict__ out) {
    // Phase-1 partials
    __shared__ float s_ps[2 * NINT];      // interior sums  [h][g*4+comp]
    __shared__ float s_pm[2 * NINT];      // interior maxes
    __shared__ float s_rs[2 * NRING];     // ring sums      [h][r]
    __shared__ float s_rm[2 * NRING];     // ring maxes
    // Final pooled maps + attn
    __shared__ float s_max[NHALO];
    __shared__ float s_avg[NHALO];
    __shared__ float s_attn[NINT];
    __shared__ float s_w[18];

    const int tid = threadIdx.x;
    const int b   = blockIdx.z;
    const int y0  = blockIdx.y * TH;
    const int x0  = blockIdx.x * TW;
    const float* __restrict__ xb = x + (size_t)b * CHW;

    if (tid < 18) s_w[tid] = w[tid];

    // ---- Phase 1: vectorized pooling ------------------------------------
    if (tid < 128) {
        // Interior float4 item: group g (0..63), channel-half h
        const int g  = tid & 63;
        const int h  = tid >> 6;
        const int py = g >> 3;
        const int px = (g & 7) * 4;
        const float4* __restrict__ p = reinterpret_cast<const float4*>(
            xb + (size_t)(h * CH2) * HWIMG + (size_t)(y0 + py) * W_ + (x0 + px));
        const int cstride = HWIMG / 4;   // float4 units per channel

        float4 s = make_float4(0.f, 0.f, 0.f, 0.f);
        float4 m = make_float4(-1e30f, -1e30f, -1e30f, -1e30f);
#pragma unroll 8
        for (int c = 0; c < CH2; c++) {
            const float4 v = __ldg(p + (size_t)c * cstride);
            s.x += v.x; s.y += v.y; s.z += v.z; s.w += v.w;
            m.x = fmaxf(m.x, v.x); m.y = fmaxf(m.y, v.y);
            m.z = fmaxf(m.z, v.z); m.w = fmaxf(m.w, v.w);
        }
        *reinterpret_cast<float4*>(&s_ps[h * NINT + g * 4]) = s;
        *reinterpret_cast<float4*>(&s_pm[h * NINT + g * 4]) = m;
    } else if (tid < 128 + 2 * NRING) {
        // Ring scalar item: pixel r (0..83), channel-half h
        const int j = tid - 128;
        const int h = (j >= NRING);
        const int r = j - h * NRING;
        int hy, hx;
        if (r < 34)      { hy = 0;              hx = r; }
        else if (r < 68) { hy = HH_ - 1;        hx = r - 34; }
        else             { const int k = r - 68; hy = 1 + (k >> 1); hx = (k & 1) ? (HW_ - 1) : 0; }
        const int Y = y0 - 1 + hy;
        const int X = x0 - 1 + hx;
        const bool inb = (Y >= 0) & (Y < H_) & (X >= 0) & (X < W_);

        float s = 0.0f, m = -1e30f;
        if (inb) {
            const float* __restrict__ p =
                xb + (size_t)(h * CH2) * HWIMG + (size_t)Y * W_ + X;
#pragma unroll 8
            for (int c = 0; c < CH2; c++) {
                const float v = __ldg(p + (size_t)c * HWIMG);
                s += v;
                m = fmaxf(m, v);
            }
        }
        s_rs[h * NRING + r] = inb ? s : 0.0f;
        s_rm[h * NRING + r] = inb ? m : 0.0f;   // 0 for OOB = zero-pad
    }
    __syncthreads();

    // ---- Combine partials -> final pooled maps (halo-indexed) -----------
    for (int t = tid; t < NHALO; t += NT) {
        const int hy = t / HW_;
        const int hx = t - hy * HW_;
        float sum, mx;
        if (hy >= 1 && hy <= TH && hx >= 1 && hx <= TW) {
            const int e = (hy - 1) * TW + (hx - 1);   // g*4+comp
            sum = s_ps[e] + s_ps[NINT + e];
            mx  = fmaxf(s_pm[e], s_pm[NINT + e]);
        } else {
            int r;
            if (hy == 0)            r = hx;
            else if (hy == HH_ - 1) r = 34 + hx;
            else                    r = 68 + (hy - 1) * 2 + (hx != 0);
            sum = s_rs[r] + s_rs[NRING + r];
            mx  = fmaxf(s_rm[r], s_rm[NRING + r]);
        }
        s_avg[t] = sum * (1.0f / C_);
        s_max[t] = mx;
    }
    __syncthreads();

    // ---- Phase 2: 3x3 conv (concat [max, avg]) + sigmoid ----------------
    if (tid < NINT) {
        const int y  = tid >> 5;
        const int xq = tid & 31;
        float acc = 0.0f;
#pragma unroll
        for (int dy = 0; dy < 3; dy++) {
#pragma unroll
            for (int dx = 0; dx < 3; dx++) {
                const int hi = (y + dy) * HW_ + (xq + dx);
                acc += s_w[dy * 3 + dx]     * s_max[hi];
                acc += s_w[9 + dy * 3 + dx] * s_avg[hi];
            }
        }
        s_attn[tid] = 1.0f / (1.0f + expf(-acc));
    }
    __syncthreads();

    // ---- Phase 3: re-read tile (L2-hot), multiply, streamed stores ------
    const int g  = tid & 63;             // float4 group in tile
    const int c0 = tid >> 6;             // 0..4
    const int py = g >> 3;
    const int px = (g & 7) * 4;
    const float4 a = *reinterpret_cast<const float4*>(&s_attn[py * TW + px]);
    const size_t base = (size_t)(y0 + py) * W_ + (x0 + px);
    float* __restrict__ ob = out + (size_t)b * CHW;

    for (int c = c0; c < C_; c += 5) {
        float4 v = __ldcs(reinterpret_cast<const float4*>(xb + (size_t)c * HWIMG + base));
        v.x *= a.x; v.y *= a.y; v.z *= a.z; v.w *= a.w;
        __stcs(reinterpret_cast<float4*>(ob + (size_t)c * HWIMG + base), v);
    }
}

extern "C" void kernel_launch(void* const* d_in, const int* in_sizes, int n_in,
                              void* d_out, int out_size) {
    const float* x = (const float*)d_in[0];
    const float* w = (const float*)d_in[1];
    float* out     = (float*)d_out;

    dim3 grid(W_ / TW, H_ / TH, B_);   // (8, 32, 16) = 4096 blocks
    spatial_attention_kernel<<<grid, NT>>>(x, w, out);
}